// round 6
// baseline (speedup 1.0000x reference)
#include <cuda_runtime.h>
#include <cstdint>

#define BB 4
#define CC 192
#define NN 8192
#define KK 16
#define COUT 192
#define TWOC 384

typedef unsigned long long ull;

__device__ float g_xt [(size_t)BB * NN * CC];   // x as [B, N, C]
__device__ float g_rel[(size_t)BB * CC * NN];   // rel as [B, C, N]
__device__ float g_part[(size_t)BB * COUT * NN]; // x-half partial sums

// ---------------------------------------------------------------------------
// Kernel 1: per-batch transpose x [C, N] -> g_xt [N, C]
// ---------------------------------------------------------------------------
__global__ void transpose_kernel(const float* __restrict__ in, float* __restrict__ outp) {
    __shared__ float tile[32][33];
    int n0 = blockIdx.x * 32;
    int c0 = blockIdx.y * 32;
    int tx = threadIdx.x, ty = threadIdx.y;
#pragma unroll
    for (int i = 0; i < 32; i += 8)
        tile[ty + i][tx] = in[(size_t)(c0 + ty + i) * NN + n0 + tx];
    __syncthreads();
#pragma unroll
    for (int i = 0; i < 32; i += 8)
        outp[(size_t)(n0 + ty + i) * CC + c0 + tx] = tile[tx][ty + i];
}

// ---------------------------------------------------------------------------
// Kernel 2: per-batch gather + max-relative -> g_rel [C, N]
// ---------------------------------------------------------------------------
#define GA_NODES 32
#define SR_S 33

__global__ __launch_bounds__(256)
void gather_kernel(const int* __restrict__ ej, const int* __restrict__ ei,
                   const float* __restrict__ bx, float* __restrict__ relb) {
    __shared__ float srel[CC * SR_S];
    __shared__ int   sj[GA_NODES * KK];
    __shared__ int   si[GA_NODES * KK];

    const int tid = threadIdx.x;
    const int n0  = blockIdx.x * GA_NODES;

    for (int t = tid; t < GA_NODES * KK; t += 256) {
        sj[t] = ej[(size_t)n0 * KK + t];
        si[t] = ei[(size_t)n0 * KK + t];
    }
    __syncthreads();

    const int wid  = tid >> 5;
    const int lane = tid & 31;
    const int cb   = lane * 2;

#pragma unroll
    for (int t = 0; t < 2; t++) {
        const int nA = wid + t * 16;
        const int nB = nA + 8;
        float2 a0 = make_float2(-3.0e38f, -3.0e38f), a1 = a0, a2 = a0;
        float2 b0 = a0, b1 = a0, b2 = a0;
        const int* sjA = sj + nA * KK; const int* siA = si + nA * KK;
        const int* sjB = sj + nB * KK; const int* siB = si + nB * KK;
#pragma unroll 2
        for (int k = 0; k < KK; k++) {
            const float* pjA = bx + (size_t)sjA[k] * CC + cb;
            const float* piA = bx + (size_t)siA[k] * CC + cb;
            const float* pjB = bx + (size_t)sjB[k] * CC + cb;
            const float* piB = bx + (size_t)siB[k] * CC + cb;
            float2 ja0 = *(const float2*)(pjA);       float2 ia0 = *(const float2*)(piA);
            float2 ja1 = *(const float2*)(pjA + 64);  float2 ia1 = *(const float2*)(piA + 64);
            float2 ja2 = *(const float2*)(pjA + 128); float2 ia2 = *(const float2*)(piA + 128);
            float2 jb0 = *(const float2*)(pjB);       float2 ib0 = *(const float2*)(piB);
            float2 jb1 = *(const float2*)(pjB + 64);  float2 ib1 = *(const float2*)(piB + 64);
            float2 jb2 = *(const float2*)(pjB + 128); float2 ib2 = *(const float2*)(piB + 128);
            a0.x = fmaxf(a0.x, ja0.x - ia0.x); a0.y = fmaxf(a0.y, ja0.y - ia0.y);
            a1.x = fmaxf(a1.x, ja1.x - ia1.x); a1.y = fmaxf(a1.y, ja1.y - ia1.y);
            a2.x = fmaxf(a2.x, ja2.x - ia2.x); a2.y = fmaxf(a2.y, ja2.y - ia2.y);
            b0.x = fmaxf(b0.x, jb0.x - ib0.x); b0.y = fmaxf(b0.y, jb0.y - ib0.y);
            b1.x = fmaxf(b1.x, jb1.x - ib1.x); b1.y = fmaxf(b1.y, jb1.y - ib1.y);
            b2.x = fmaxf(b2.x, jb2.x - ib2.x); b2.y = fmaxf(b2.y, jb2.y - ib2.y);
        }
        srel[(cb)       * SR_S + nA] = a0.x; srel[(cb + 1)   * SR_S + nA] = a0.y;
        srel[(cb + 64)  * SR_S + nA] = a1.x; srel[(cb + 65)  * SR_S + nA] = a1.y;
        srel[(cb + 128) * SR_S + nA] = a2.x; srel[(cb + 129) * SR_S + nA] = a2.y;
        srel[(cb)       * SR_S + nB] = b0.x; srel[(cb + 1)   * SR_S + nB] = b0.y;
        srel[(cb + 64)  * SR_S + nB] = b1.x; srel[(cb + 65)  * SR_S + nB] = b1.y;
        srel[(cb + 128) * SR_S + nB] = b2.x; srel[(cb + 129) * SR_S + nB] = b2.y;
    }
    __syncthreads();

    float* ro = relb + n0;
    for (int t = tid; t < CC * GA_NODES; t += 256) {
        int c = t >> 5, n = t & 31;
        ro[(size_t)c * NN + n] = srel[c * SR_S + n];
    }
}

// ---------------------------------------------------------------------------
// GEMM halves: 512 threads, 64-node tile, 3 outputs x 8 nodes per thread.
// ---------------------------------------------------------------------------
#define GT 512
#define GN 64
#define KC 32
#define NCHH (CC / KC)       // 6
#define WPD 33

#define YCH_BYTES (KC * GN * 4)
#define WSD_OFF   YCH_BYTES
#define GEMM_SMEM (WSD_OFF + COUT * WPD * 8)   // 58880

__device__ __forceinline__ void gemm_half(const float* __restrict__ ysrc,
                                          const float* __restrict__ W, int wc0,
                                          int tid, int oi, int ni,
                                          float* ych, float2* wsd, ull acc[3][4]) {
    ull* wsq = (ull*)wsd;
    const ull* wp = wsq + oi * 3 * WPD;

    float4 pf;
    {
        pf = *(const float4*)(ysrc + (size_t)(tid >> 4) * NN + (tid & 15) * 4);
    }

    for (int ch = 0; ch < NCHH; ch++) {
        ((float4*)ych)[tid] = pf;
        const float* wsrc = W + wc0 + ch * KC;
        for (int t = tid; t < COUT * KC; t += GT) {
            int o = t >> 5, k = t & 31;
            float v = wsrc[(size_t)o * TWOC + k];
            wsd[o * WPD + k] = make_float2(v, v);
        }
        __syncthreads();

        if (ch + 1 < NCHH) {
            const float* s = ysrc + (size_t)(ch + 1) * KC * NN;
            pf = *(const float4*)(s + (size_t)(tid >> 4) * NN + (tid & 15) * 4);
        }

#pragma unroll 8
        for (int kk = 0; kk < KC; kk++) {
            longlong2 qa = *(const longlong2*)(ych + kk * GN + ni * 4);
            longlong2 qb = *(const longlong2*)(ych + kk * GN + 32 + ni * 4);
            ull y2[4] = { (ull)qa.x, (ull)qa.y, (ull)qb.x, (ull)qb.y };
#pragma unroll
            for (int m = 0; m < 3; m++) {
                ull w = wp[m * WPD + kk];
#pragma unroll
                for (int p = 0; p < 4; p++)
                    asm("fma.rn.f32x2 %0, %1, %2, %3;"
                        : "=l"(acc[m][p]) : "l"(w), "l"(y2[p]), "l"(acc[m][p]));
            }
        }
        __syncthreads();
    }
}

// x-half GEMM (all batches, gather-independent): raw partials to g_part.
__global__ __launch_bounds__(GT, 2)
void gemm_x_kernel(const float* __restrict__ x, const float* __restrict__ W) {
    extern __shared__ char smem[];
    float*  ych = (float*)smem;
    float2* wsd = (float2*)(smem + WSD_OFF);

    const int tid = threadIdx.x;
    const int bid = blockIdx.x;
    const int b   = bid >> 7;
    const int n0  = (bid & 127) * GN;
    const int oi  = tid >> 3;
    const int ni  = tid & 7;

    ull acc[3][4];
#pragma unroll
    for (int m = 0; m < 3; m++)
#pragma unroll
        for (int p = 0; p < 4; p++) acc[m][p] = 0ULL;

    gemm_half(x + (size_t)b * CC * NN + n0, W, 0, tid, oi, ni, ych, wsd, acc);

    float* pb = g_part + (size_t)b * COUT * NN + n0 + ni * 4;
#pragma unroll
    for (int m = 0; m < 3; m++) {
        float* op = pb + (size_t)(oi * 3 + m) * NN;
        float4 v0, v1; float a, c;
        asm("mov.b64 {%0, %1}, %2;" : "=f"(a), "=f"(c) : "l"(acc[m][0])); v0.x = a; v0.y = c;
        asm("mov.b64 {%0, %1}, %2;" : "=f"(a), "=f"(c) : "l"(acc[m][1])); v0.z = a; v0.w = c;
        asm("mov.b64 {%0, %1}, %2;" : "=f"(a), "=f"(c) : "l"(acc[m][2])); v1.x = a; v1.y = c;
        asm("mov.b64 {%0, %1}, %2;" : "=f"(a), "=f"(c) : "l"(acc[m][3])); v1.z = a; v1.w = c;
        *(float4*)(op)      = v0;
        *(float4*)(op + 32) = v1;
    }
}

// rel-half GEMM, one batch per launch: adds partial + bias, relu, writes out.
__global__ __launch_bounds__(GT, 2)
void gemm_rel_kernel(int b, const float* __restrict__ W,
                     const float* __restrict__ bias, float* __restrict__ out) {
    extern __shared__ char smem[];
    float*  ych = (float*)smem;
    float2* wsd = (float2*)(smem + WSD_OFF);

    const int tid = threadIdx.x;
    const int n0  = blockIdx.x * GN;
    const int oi  = tid >> 3;
    const int ni  = tid & 7;

    float bv[3];
#pragma unroll
    for (int m = 0; m < 3; m++) bv[m] = bias[oi * 3 + m];

    ull acc[3][4];
#pragma unroll
    for (int m = 0; m < 3; m++)
#pragma unroll
        for (int p = 0; p < 4; p++) acc[m][p] = 0ULL;

    gemm_half(g_rel + (size_t)b * CC * NN + n0, W, CC, tid, oi, ni, ych, wsd, acc);

    const float* pb = g_part + (size_t)b * COUT * NN + n0 + ni * 4;
    float*       ob = out    + (size_t)b * COUT * NN + n0 + ni * 4;
#pragma unroll
    for (int m = 0; m < 3; m++) {
        const float* pp = pb + (size_t)(oi * 3 + m) * NN;
        float4 p0 = *(const float4*)(pp);
        float4 p1 = *(const float4*)(pp + 32);
        float4 v0, v1; float a, c;
        asm("mov.b64 {%0, %1}, %2;" : "=f"(a), "=f"(c) : "l"(acc[m][0]));
        v0.x = fmaxf(p0.x + a + bv[m], 0.0f); v0.y = fmaxf(p0.y + c + bv[m], 0.0f);
        asm("mov.b64 {%0, %1}, %2;" : "=f"(a), "=f"(c) : "l"(acc[m][1]));
        v0.z = fmaxf(p0.z + a + bv[m], 0.0f); v0.w = fmaxf(p0.w + c + bv[m], 0.0f);
        asm("mov.b64 {%0, %1}, %2;" : "=f"(a), "=f"(c) : "l"(acc[m][2]));
        v1.x = fmaxf(p1.x + a + bv[m], 0.0f); v1.y = fmaxf(p1.y + c + bv[m], 0.0f);
        asm("mov.b64 {%0, %1}, %2;" : "=f"(a), "=f"(c) : "l"(acc[m][3]));
        v1.z = fmaxf(p1.z + a + bv[m], 0.0f); v1.w = fmaxf(p1.w + c + bv[m], 0.0f);
        float* op = ob + (size_t)(oi * 3 + m) * NN;
        *(float4*)(op)      = v0;
        *(float4*)(op + 32) = v1;
    }
}

// ---------------------------------------------------------------------------
// Launch: per-batch pipeline.
//   sA: [transpose(b); gather(b); record eG[b]] for b=0..3
//   sB: gemm_x (all batches); record eX
//   s0: wait eX; for b: wait eG[b]; gemm_rel(b)
// ---------------------------------------------------------------------------
extern "C" void kernel_launch(void* const* d_in, const int* in_sizes, int n_in,
                              void* d_out, int out_size) {
    const float* x    = (const float*)d_in[0];
    const int*   edge = (const int*)d_in[2];
    const float* W    = (const float*)d_in[3];
    const float* bias = (const float*)d_in[4];
    float*       out  = (float*)d_out;

    static cudaStream_t sA = nullptr, sB = nullptr;
    static cudaEvent_t  eFork = nullptr, eX = nullptr, eG[BB];
    if (sA == nullptr) {
        cudaStreamCreateWithFlags(&sA, cudaStreamNonBlocking);
        cudaStreamCreateWithFlags(&sB, cudaStreamNonBlocking);
        cudaEventCreateWithFlags(&eFork, cudaEventDisableTiming);
        cudaEventCreateWithFlags(&eX, cudaEventDisableTiming);
        for (int b = 0; b < BB; b++)
            cudaEventCreateWithFlags(&eG[b], cudaEventDisableTiming);
        cudaFuncSetAttribute(gemm_x_kernel,
                             cudaFuncAttributeMaxDynamicSharedMemorySize, GEMM_SMEM);
        cudaFuncSetAttribute(gemm_rel_kernel,
                             cudaFuncAttributeMaxDynamicSharedMemorySize, GEMM_SMEM);
    }

    float* g_xt_p;  cudaGetSymbolAddress((void**)&g_xt_p,  g_xt);
    float* g_rel_p; cudaGetSymbolAddress((void**)&g_rel_p, g_rel);

    cudaEventRecord(eFork, 0);
    cudaStreamWaitEvent(sA, eFork, 0);
    cudaStreamWaitEvent(sB, eFork, 0);

    // sB: gather-independent x-half GEMM over all batches
    gemm_x_kernel<<<BB * (NN / GN), GT, GEMM_SMEM, sB>>>(x, W);
    cudaEventRecord(eX, sB);
    cudaStreamWaitEvent(0, eX, 0);

    // sA: per-batch transpose -> gather
    for (int b = 0; b < BB; b++) {
        transpose_kernel<<<dim3(NN / 32, CC / 32), dim3(32, 8), 0, sA>>>(
            x + (size_t)b * CC * NN, g_xt_p + (size_t)b * NN * CC);
        gather_kernel<<<NN / GA_NODES, 256, 0, sA>>>(
            edge + (size_t)b * NN * KK,
            edge + (size_t)(BB + b) * NN * KK,
            g_xt_p + (size_t)b * NN * CC,
            g_rel_p + (size_t)b * CC * NN);
        cudaEventRecord(eG[b], sA);
    }

    // s0: per-batch rel-half GEMM as soon as its gather lands
    for (int b = 0; b < BB; b++) {
        cudaStreamWaitEvent(0, eG[b], 0);
        gemm_rel_kernel<<<NN / GN, GT, GEMM_SMEM>>>(b, W, bias, out);
    }
}